// round 3
// baseline (speedup 1.0000x reference)
#include <cuda_runtime.h>

#define EPSV 1e-6f

typedef unsigned long long u64;

__device__ __forceinline__ u64 pack2(float x, float y){
    u64 r; asm("mov.b64 %0, {%1, %2};" : "=l"(r) : "f"(x), "f"(y)); return r;
}
__device__ __forceinline__ u64 ffma2(u64 a, u64 b, u64 c){
    u64 d; asm("fma.rn.f32x2 %0, %1, %2, %3;" : "=l"(d) : "l"(a), "l"(b), "l"(c)); return d;
}
__device__ __forceinline__ float2 unpack2(u64 a){
    float2 f; asm("mov.b64 {%0, %1}, %2;" : "=f"(f.x), "=f"(f.y) : "l"(a)); return f;
}

#define BB 8
#define HH 256
#define WW 256
#define CC 64
#define HID 128
#define OC1 256
#define NPIX (BB*HH*WW)

// Scratch (static __device__ globals per harness rules)
__device__ float g_t1[(size_t)NPIX * OC1];   // 512 MB: pw1 output
__device__ float g_y [(size_t)NPIX * HID];   // 256 MB: gated dw output
__device__ float g_x2[(size_t)NPIX * CC];    // 128 MB: stage-1 residual output
__device__ float g_part[BB * 1024 * HID];    // GAP partials per block
__device__ float g_attn[BB * HID];           // channel attention

// ---------------------------------------------------------------------------
// K1: LayerNorm1 + pw1 (64 -> 256)
// ---------------------------------------------------------------------------
__global__ void k1_ln_pw1(const float* __restrict__ x, const float* __restrict__ g1,
                          const float* __restrict__ b1, const float* __restrict__ W,
                          const float* __restrict__ bias)
{
    extern __shared__ float sm[];
    float* sW  = sm;                 // 64*256
    float* sB  = sm + 64*256;        // 256
    float* sG  = sB + 256;           // 64
    float* sBe = sG + 64;            // 64
    int tid = threadIdx.x;
    for (int i = tid; i < 64*256; i += 256) sW[i] = W[i];
    sB[tid] = bias[tid];
    if (tid < 64) { sG[tid] = g1[tid]; sBe[tid] = b1[tid]; }
    __syncthreads();

    size_t p = (size_t)blockIdx.x * 256 + tid;
    const float4* xp = (const float4*)(x + p * 64);
    float4 xv[16];
    #pragma unroll
    for (int q = 0; q < 16; q++) xv[q] = xp[q];
    float s = 0.f, ss = 0.f;
    #pragma unroll
    for (int q = 0; q < 16; q++){
        float4 v = xv[q];
        s += v.x + v.y + v.z + v.w;
        ss = fmaf(v.x,v.x, fmaf(v.y,v.y, fmaf(v.z,v.z, fmaf(v.w,v.w, ss))));
    }
    float mean = s * (1.f/64.f);
    float var  = fmaf(-mean, mean, ss * (1.f/64.f));
    float rstd = rsqrtf(var + EPSV);
    float ln[64];
    #pragma unroll
    for (int q = 0; q < 16; q++){
        float4 v = xv[q];
        ln[4*q+0] = fmaf((v.x-mean)*rstd, sG[4*q+0], sBe[4*q+0]);
        ln[4*q+1] = fmaf((v.y-mean)*rstd, sG[4*q+1], sBe[4*q+1]);
        ln[4*q+2] = fmaf((v.z-mean)*rstd, sG[4*q+2], sBe[4*q+2]);
        ln[4*q+3] = fmaf((v.w-mean)*rstd, sG[4*q+3], sBe[4*q+3]);
    }
    float* outp = g_t1 + p * 256;
    #pragma unroll 1
    for (int oc0 = 0; oc0 < 256; oc0 += 32){
        u64 acc[16];
        const u64* bb = (const u64*)(sB + oc0);
        #pragma unroll
        for (int j = 0; j < 16; j++) acc[j] = bb[j];
        #pragma unroll
        for (int k = 0; k < 64; k++){
            u64 a = pack2(ln[k], ln[k]);
            const ulonglong2* wr = (const ulonglong2*)(sW + k*256 + oc0);
            #pragma unroll
            for (int q = 0; q < 8; q++){
                ulonglong2 w = wr[q];
                acc[2*q]   = ffma2(a, w.x, acc[2*q]);
                acc[2*q+1] = ffma2(a, w.y, acc[2*q+1]);
            }
        }
        float4* op = (float4*)(outp + oc0);
        #pragma unroll
        for (int q = 0; q < 8; q++){
            float2 a = unpack2(acc[2*q]);
            float2 b = unpack2(acc[2*q+1]);
            op[q] = make_float4(a.x, a.y, b.x, b.y);
        }
    }
}

// ---------------------------------------------------------------------------
// K2: depthwise 3x3 (SAME) + SimpleGate + GAP partials
// thread = channel pair (c, c+128); block = 64-pixel row segment
// ---------------------------------------------------------------------------
__global__ void k2_dw_gate(const float* __restrict__ dww, const float* __restrict__ dwb)
{
    int blk = blockIdx.x;           // b*1024 + h*4 + wt
    int b   = blk >> 10;
    int rem = blk & 1023;
    int h   = rem >> 2;
    int w0  = (rem & 3) << 6;
    int c   = threadIdx.x;          // 0..127
    int c2  = c + 128;
    float wt0[9], wt1[9];
    #pragma unroll
    for (int i = 0; i < 9; i++){ wt0[i] = dww[i*256 + c]; wt1[i] = dww[i*256 + c2]; }
    float bc0 = dwb[c], bc1 = dwb[c2];

    const float* img = g_t1 + (size_t)b * HH * WW * 256;
    bool v0 = (h > 0), v2 = (h < HH-1);
    const float* r0 = img + (size_t)(h-1) * WW * 256;
    const float* r1 = img + (size_t)h     * WW * 256;
    const float* r2 = img + (size_t)(h+1) * WW * 256;

    float win0[9], win1[9];
    {
        int wm = w0 - 1;
        bool vm = (wm >= 0);
        win0[0] = (v0 && vm) ? r0[(size_t)wm*256 + c ] : 0.f;
        win0[3] =  vm        ? r1[(size_t)wm*256 + c ] : 0.f;
        win0[6] = (v2 && vm) ? r2[(size_t)wm*256 + c ] : 0.f;
        win1[0] = (v0 && vm) ? r0[(size_t)wm*256 + c2] : 0.f;
        win1[3] =  vm        ? r1[(size_t)wm*256 + c2] : 0.f;
        win1[6] = (v2 && vm) ? r2[(size_t)wm*256 + c2] : 0.f;
        win0[1] = v0 ? r0[(size_t)w0*256 + c ] : 0.f;
        win0[4] =      r1[(size_t)w0*256 + c ];
        win0[7] = v2 ? r2[(size_t)w0*256 + c ] : 0.f;
        win1[1] = v0 ? r0[(size_t)w0*256 + c2] : 0.f;
        win1[4] =      r1[(size_t)w0*256 + c2];
        win1[7] = v2 ? r2[(size_t)w0*256 + c2] : 0.f;
    }
    float* yrow = g_y + ((size_t)(b*HH + h) * WW) * 128;
    float gap = 0.f;
    for (int w = w0; w < w0 + 64; w++){
        int wp = w + 1;
        bool vp = (wp < WW);
        win0[2] = (v0 && vp) ? r0[(size_t)wp*256 + c ] : 0.f;
        win0[5] =  vp        ? r1[(size_t)wp*256 + c ] : 0.f;
        win0[8] = (v2 && vp) ? r2[(size_t)wp*256 + c ] : 0.f;
        win1[2] = (v0 && vp) ? r0[(size_t)wp*256 + c2] : 0.f;
        win1[5] =  vp        ? r1[(size_t)wp*256 + c2] : 0.f;
        win1[8] = (v2 && vp) ? r2[(size_t)wp*256 + c2] : 0.f;
        float a = bc0, bb = bc1;
        #pragma unroll
        for (int i = 0; i < 9; i++){ a = fmaf(win0[i], wt0[i], a); bb = fmaf(win1[i], wt1[i], bb); }
        float yv = a * bb;
        yrow[(size_t)w * 128 + c] = yv;
        gap += yv;
        #pragma unroll
        for (int r = 0; r < 3; r++){
            win0[r*3+0] = win0[r*3+1]; win0[r*3+1] = win0[r*3+2];
            win1[r*3+0] = win1[r*3+1]; win1[r*3+1] = win1[r*3+2];
        }
    }
    g_part[(size_t)blk * 128 + c] = gap;
}

// ---------------------------------------------------------------------------
// K3: GAP reduce + SCA (128 -> 128 on pooled means)
// ---------------------------------------------------------------------------
__global__ void k3_sca(const float* __restrict__ scaw, const float* __restrict__ scab)
{
    __shared__ float smn[128];
    int b = blockIdx.x, c = threadIdx.x;
    const float* p = g_part + (size_t)b * 1024 * 128 + c;
    float s = 0.f;
    #pragma unroll 8
    for (int i = 0; i < 1024; i++) s += p[(size_t)i * 128];
    smn[c] = s * (1.f / 65536.f);
    __syncthreads();
    float a = scab[c];
    #pragma unroll 8
    for (int k = 0; k < 128; k++) a = fmaf(smn[k], scaw[k*128 + c], a);
    g_attn[b*128 + c] = a;
}

// ---------------------------------------------------------------------------
// K4a: y*attn -> pw2 (128 -> 64) -> x2 = x + .*beta
// ---------------------------------------------------------------------------
__global__ void k4a_att_pw2(const float* __restrict__ x, const float* __restrict__ W2,
                            const float* __restrict__ b2, const float* __restrict__ beta)
{
    __shared__ __align__(16) float sW[128*64];
    __shared__ __align__(16) float sA[128];
    __shared__ __align__(16) float sB2[64];
    __shared__ __align__(16) float sBeta[64];
    int tid = threadIdx.x;
    int b = blockIdx.x >> 8;     // 256 blocks per image
    for (int i = tid; i < 128*64; i += 256) sW[i] = W2[i];
    if (tid < 128) sA[tid] = g_attn[b*128 + tid];
    if (tid < 64) { sB2[tid] = b2[tid]; sBeta[tid] = beta[tid]; }
    __syncthreads();
    size_t p = (size_t)blockIdx.x * 256 + tid;
    u64 acc[32];
    const u64* bb = (const u64*)sB2;
    #pragma unroll
    for (int j = 0; j < 32; j++) acc[j] = bb[j];
    const float4* yp = (const float4*)(g_y + p * 128);
    #pragma unroll 4
    for (int c4 = 0; c4 < 32; c4++){
        float4 yv = yp[c4];
        float va[4];
        va[0] = yv.x * sA[4*c4+0]; va[1] = yv.y * sA[4*c4+1];
        va[2] = yv.z * sA[4*c4+2]; va[3] = yv.w * sA[4*c4+3];
        #pragma unroll
        for (int r = 0; r < 4; r++){
            u64 a = pack2(va[r], va[r]);
            const ulonglong2* wr = (const ulonglong2*)(sW + (4*c4+r)*64);
            #pragma unroll
            for (int q = 0; q < 16; q++){
                ulonglong2 w = wr[q];
                acc[2*q]   = ffma2(a, w.x, acc[2*q]);
                acc[2*q+1] = ffma2(a, w.y, acc[2*q+1]);
            }
        }
    }
    const float4* xp = (const float4*)(x + p * 64);
    float4* op = (float4*)(g_x2 + p * 64);
    #pragma unroll
    for (int q = 0; q < 16; q++){
        float4 xv = xp[q];
        float2 a = unpack2(acc[2*q]);
        float2 c = unpack2(acc[2*q+1]);
        float4 o;
        o.x = fmaf(a.x, sBeta[4*q+0], xv.x);
        o.y = fmaf(a.y, sBeta[4*q+1], xv.y);
        o.z = fmaf(c.x, sBeta[4*q+2], xv.z);
        o.w = fmaf(c.y, sBeta[4*q+3], xv.w);
        op[q] = o;
    }
}

// ---------------------------------------------------------------------------
// K4b: LN2 -> pw3 (64 -> 256) -> gate -> pw4 (128 -> 64) -> out = x2 + .*gamma
// W3 stored interleaved as pairs (W3[k][j], W3[k][128+j]) so gate halves are adjacent
// ---------------------------------------------------------------------------
__global__ void k4b_ln_pw34(const float* __restrict__ W3, const float* __restrict__ b3,
                            const float* __restrict__ W4, const float* __restrict__ b4,
                            const float* __restrict__ g2, const float* __restrict__ bb2,
                            const float* __restrict__ gamma, float* __restrict__ out)
{
    extern __shared__ float sm[];
    float* sW3 = sm;             // 16384 floats (interleaved pairs)
    float* sW4 = sm + 16384;     // 8192
    float* sB3 = sW4 + 8192;     // 256 (interleaved pairs)
    float* sB4 = sB3 + 256;      // 64
    float* sG  = sB4 + 64;       // 64
    float* sBe = sG + 64;        // 64
    float* sGa = sBe + 64;       // 64
    int tid = threadIdx.x;       // 128
    for (int i = tid; i < 64*256; i += 128){
        int k = i >> 8, t = i & 255, j = t >> 1, hh = t & 1;
        sW3[i] = W3[k*256 + hh*128 + j];
    }
    for (int i = tid; i < 128*64; i += 128) sW4[i] = W4[i];
    sB3[2*tid] = b3[tid]; sB3[2*tid+1] = b3[128+tid];
    if (tid < 64){ sB4[tid]=b4[tid]; sG[tid]=g2[tid]; sBe[tid]=bb2[tid]; sGa[tid]=gamma[tid]; }
    __syncthreads();

    size_t p = (size_t)blockIdx.x * 128 + tid;
    const float4* xp = (const float4*)(g_x2 + p * 64);
    float s = 0.f, ssum = 0.f;
    #pragma unroll
    for (int q = 0; q < 16; q++){
        float4 v = xp[q];
        s += v.x+v.y+v.z+v.w;
        ssum = fmaf(v.x,v.x,fmaf(v.y,v.y,fmaf(v.z,v.z,fmaf(v.w,v.w,ssum))));
    }
    float mean = s * (1.f/64.f);
    float var  = fmaf(-mean, mean, ssum * (1.f/64.f));
    float rstd = rsqrtf(var + EPSV);
    float ln[64];
    #pragma unroll
    for (int q = 0; q < 16; q++){
        float4 v = xp[q];   // L1 re-hit
        ln[4*q+0] = fmaf((v.x-mean)*rstd, sG[4*q+0], sBe[4*q+0]);
        ln[4*q+1] = fmaf((v.y-mean)*rstd, sG[4*q+1], sBe[4*q+1]);
        ln[4*q+2] = fmaf((v.z-mean)*rstd, sG[4*q+2], sBe[4*q+2]);
        ln[4*q+3] = fmaf((v.w-mean)*rstd, sG[4*q+3], sBe[4*q+3]);
    }
    u64 acc[32];
    const u64* b4p = (const u64*)sB4;
    #pragma unroll
    for (int j = 0; j < 32; j++) acc[j] = b4p[j];
    const u64* b3p = (const u64*)sB3;
    #pragma unroll 1
    for (int jc = 0; jc < 16; jc++){
        u64 t3[8];
        #pragma unroll
        for (int ji = 0; ji < 8; ji++) t3[ji] = b3p[jc*8 + ji];
        #pragma unroll
        for (int k = 0; k < 64; k++){
            u64 a = pack2(ln[k], ln[k]);
            const ulonglong2* wr = (const ulonglong2*)(sW3 + k*256 + jc*16);
            #pragma unroll
            for (int q = 0; q < 4; q++){
                ulonglong2 w = wr[q];
                t3[2*q]   = ffma2(a, w.x, t3[2*q]);
                t3[2*q+1] = ffma2(a, w.y, t3[2*q+1]);
            }
        }
        #pragma unroll
        for (int ji = 0; ji < 8; ji++){
            float2 t = unpack2(t3[ji]);
            float gv = t.x * t.y;                 // SimpleGate
            u64 gg = pack2(gv, gv);
            const ulonglong2* wr = (const ulonglong2*)(sW4 + (jc*8 + ji)*64);
            #pragma unroll
            for (int q = 0; q < 16; q++){
                ulonglong2 w = wr[q];
                acc[2*q]   = ffma2(gg, w.x, acc[2*q]);
                acc[2*q+1] = ffma2(gg, w.y, acc[2*q+1]);
            }
        }
    }
    float4* op = (float4*)(out + p*64);
    #pragma unroll
    for (int q = 0; q < 16; q++){
        float4 xv = xp[q];
        float2 a = unpack2(acc[2*q]);
        float2 c = unpack2(acc[2*q+1]);
        float4 o;
        o.x = fmaf(a.x, sGa[4*q+0], xv.x);
        o.y = fmaf(a.y, sGa[4*q+1], xv.y);
        o.z = fmaf(c.x, sGa[4*q+2], xv.z);
        o.w = fmaf(c.y, sGa[4*q+3], xv.w);
        op[q] = o;
    }
}

// ---------------------------------------------------------------------------
extern "C" void kernel_launch(void* const* d_in, const int* in_sizes, int n_in,
                              void* d_out, int out_size)
{
    const float* x    = (const float*)d_in[0];
    const float* ln1g = (const float*)d_in[1];
    const float* ln1b = (const float*)d_in[2];
    const float* pw1w = (const float*)d_in[3];
    const float* pw1b = (const float*)d_in[4];
    const float* dww  = (const float*)d_in[5];
    const float* dwb  = (const float*)d_in[6];
    const float* scaw = (const float*)d_in[7];
    const float* scab = (const float*)d_in[8];
    const float* pw2w = (const float*)d_in[9];
    const float* pw2b = (const float*)d_in[10];
    const float* beta = (const float*)d_in[11];
    const float* ln2g = (const float*)d_in[12];
    const float* ln2b = (const float*)d_in[13];
    const float* pw3w = (const float*)d_in[14];
    const float* pw3b = (const float*)d_in[15];
    const float* pw4w = (const float*)d_in[16];
    const float* pw4b = (const float*)d_in[17];
    const float* gam  = (const float*)d_in[18];
    float* out = (float*)d_out;

    int smem1  = (64*256 + 256 + 64 + 64) * 4;                       // 67072
    int smem4b = (16384 + 8192 + 256 + 64 + 64 + 64 + 64) * 4;       // 100352
    cudaFuncSetAttribute(k1_ln_pw1,  cudaFuncAttributeMaxDynamicSharedMemorySize, smem1);
    cudaFuncSetAttribute(k4b_ln_pw34, cudaFuncAttributeMaxDynamicSharedMemorySize, smem4b);

    k1_ln_pw1 <<<NPIX/256, 256, smem1>>>(x, ln1g, ln1b, pw1w, pw1b);
    k2_dw_gate<<<BB*1024, 128>>>(dww, dwb);
    k3_sca    <<<BB, 128>>>(scaw, scab);
    k4a_att_pw2<<<NPIX/256, 256>>>(x, pw2w, pw2b, beta);
    k4b_ln_pw34<<<NPIX/128, 128, smem4b>>>(pw3w, pw3b, pw4w, pw4b, ln2g, ln2b, gam, out);
}

// round 4
// speedup vs baseline: 1.3362x; 1.3362x over previous
#include <cuda_runtime.h>

#define EPSV 1e-6f

typedef unsigned long long u64;

__device__ __forceinline__ u64 pack2(float x, float y){
    u64 r; asm("mov.b64 %0, {%1, %2};" : "=l"(r) : "f"(x), "f"(y)); return r;
}
__device__ __forceinline__ u64 ffma2(u64 a, u64 b, u64 c){
    u64 d; asm("fma.rn.f32x2 %0, %1, %2, %3;" : "=l"(d) : "l"(a), "l"(b), "l"(c)); return d;
}
__device__ __forceinline__ float2 unpack2(u64 a){
    float2 f; asm("mov.b64 {%0, %1}, %2;" : "=f"(f.x), "=f"(f.y) : "l"(a)); return f;
}

#define BB 8
#define HH 256
#define WW 256
#define CC 64
#define HID 128
#define OC1 256
#define NPIX (BB*HH*WW)
#define PXT 128                 // pixels per GEMM block
#define AST 132                 // act tile row stride (floats): 128 + 4, 16B-aligned

// Scratch (static __device__ globals per harness rules)
__device__ float g_t1[(size_t)NPIX * OC1];   // pw1 output
__device__ float g_y [(size_t)NPIX * HID];   // gated dw output; later reused for k4b1 gate output
__device__ float g_x2[(size_t)NPIX * CC];    // stage-1 residual output
__device__ float g_part[BB * 1024 * HID];    // GAP partials per block
__device__ float g_attn[BB * HID];           // channel attention

// One register-tile GEMM step: 4 px (a4) x 8 outs (w0,w1 as 4 f32-pairs), 16 FFMA2.
#define GEMM_STEP(aPtr, wPtr) do { \
    float4 a4 = *(const float4*)(aPtr); \
    const ulonglong2* wr_ = (const ulonglong2*)(wPtr); \
    ulonglong2 w0 = wr_[0], w1 = wr_[1]; \
    u64 a0 = pack2(a4.x, a4.x), a1 = pack2(a4.y, a4.y); \
    u64 a2 = pack2(a4.z, a4.z), a3 = pack2(a4.w, a4.w); \
    acc[ 0]=ffma2(a0,w0.x,acc[ 0]); acc[ 1]=ffma2(a0,w0.y,acc[ 1]); acc[ 2]=ffma2(a0,w1.x,acc[ 2]); acc[ 3]=ffma2(a0,w1.y,acc[ 3]); \
    acc[ 4]=ffma2(a1,w0.x,acc[ 4]); acc[ 5]=ffma2(a1,w0.y,acc[ 5]); acc[ 6]=ffma2(a1,w1.x,acc[ 6]); acc[ 7]=ffma2(a1,w1.y,acc[ 7]); \
    acc[ 8]=ffma2(a2,w0.x,acc[ 8]); acc[ 9]=ffma2(a2,w0.y,acc[ 9]); acc[10]=ffma2(a2,w1.x,acc[10]); acc[11]=ffma2(a2,w1.y,acc[11]); \
    acc[12]=ffma2(a3,w0.x,acc[12]); acc[13]=ffma2(a3,w0.y,acc[13]); acc[14]=ffma2(a3,w1.x,acc[14]); acc[15]=ffma2(a3,w1.y,acc[15]); \
} while(0)

// ---------------------------------------------------------------------------
// K1: LayerNorm1 + pw1 (64 -> 256), tiled GEMM. 128 px/block, 256 threads.
// thread tile: 4 px x 8 outs; outer loop over 4 output chunks of 64.
// ---------------------------------------------------------------------------
__global__ void __launch_bounds__(256) k1_ln_pw1(
    const float* __restrict__ x, const float* __restrict__ g1,
    const float* __restrict__ b1, const float* __restrict__ W,
    const float* __restrict__ bias)
{
    extern __shared__ float sm[];
    float* sW  = sm;                 // 64*256 = 16384
    float* aT  = sm + 16384;         // 64*AST = 8448 (transposed LN tile)
    float* sB  = aT + 64*AST;        // 256
    float* sG  = sB + 256;           // 64
    float* sBe = sG + 64;            // 64
    int tid = threadIdx.x;
    #pragma unroll 4
    for (int i = tid; i < 16384; i += 256) sW[i] = W[i];
    sB[tid] = bias[tid];
    if (tid < 64) { sG[tid] = g1[tid]; sBe[tid] = b1[tid]; }
    __syncthreads();

    size_t p0 = (size_t)blockIdx.x * PXT;
    // LN: 2 threads per pixel, 32 channels each
    {
        int px = tid >> 1, half = tid & 1;
        const float4* xp = (const float4*)(x + (p0 + px) * 64 + half * 32);
        float4 v[8];
        #pragma unroll
        for (int q = 0; q < 8; q++) v[q] = xp[q];
        float s = 0.f, ss = 0.f;
        #pragma unroll
        for (int q = 0; q < 8; q++){
            float4 t = v[q];
            s += t.x + t.y + t.z + t.w;
            ss = fmaf(t.x,t.x, fmaf(t.y,t.y, fmaf(t.z,t.z, fmaf(t.w,t.w, ss))));
        }
        s  += __shfl_xor_sync(0xffffffffu, s, 1);
        ss += __shfl_xor_sync(0xffffffffu, ss, 1);
        float mean = s * (1.f/64.f);
        float var  = fmaf(-mean, mean, ss * (1.f/64.f));
        float rstd = rsqrtf(var + EPSV);
        #pragma unroll
        for (int q = 0; q < 8; q++){
            float4 t = v[q];
            int ch = half*32 + 4*q;
            aT[(ch+0)*AST + px] = fmaf((t.x-mean)*rstd, sG[ch+0], sBe[ch+0]);
            aT[(ch+1)*AST + px] = fmaf((t.y-mean)*rstd, sG[ch+1], sBe[ch+1]);
            aT[(ch+2)*AST + px] = fmaf((t.z-mean)*rstd, sG[ch+2], sBe[ch+2]);
            aT[(ch+3)*AST + px] = fmaf((t.w-mean)*rstd, sG[ch+3], sBe[ch+3]);
        }
    }
    __syncthreads();

    int ip = tid & 31, jo = tid >> 5;       // warp: same jo, ip = lane
    const float* aBase = aT + ip * 4;
    float* outBase = g_t1 + (p0 + ip * 4) * 256;
    #pragma unroll 1
    for (int oc = 0; oc < 256; oc += 64){
        int ob = oc + jo * 8;
        u64 acc[16];
        const u64* bb = (const u64*)(sB + ob);
        #pragma unroll
        for (int p = 0; p < 4; p++){
            acc[4*p+0]=bb[0]; acc[4*p+1]=bb[1]; acc[4*p+2]=bb[2]; acc[4*p+3]=bb[3];
        }
        const float* wBase = sW + ob;
        #pragma unroll 8
        for (int k = 0; k < 64; k++){
            GEMM_STEP(aBase + k*AST, wBase + k*256);
        }
        #pragma unroll
        for (int p = 0; p < 4; p++){
            float2 r0 = unpack2(acc[4*p+0]), r1 = unpack2(acc[4*p+1]);
            float2 r2 = unpack2(acc[4*p+2]), r3 = unpack2(acc[4*p+3]);
            float4* op = (float4*)(outBase + (size_t)p*256 + ob);
            op[0] = make_float4(r0.x, r0.y, r1.x, r1.y);
            op[1] = make_float4(r2.x, r2.y, r3.x, r3.y);
        }
    }
}

// ---------------------------------------------------------------------------
// K2: depthwise 3x3 (SAME) + SimpleGate + GAP partials (unchanged)
// ---------------------------------------------------------------------------
__global__ void k2_dw_gate(const float* __restrict__ dww, const float* __restrict__ dwb)
{
    int blk = blockIdx.x;           // b*1024 + h*4 + wt
    int b   = blk >> 10;
    int rem = blk & 1023;
    int h   = rem >> 2;
    int w0  = (rem & 3) << 6;
    int c   = threadIdx.x;          // 0..127
    int c2  = c + 128;
    float wt0[9], wt1[9];
    #pragma unroll
    for (int i = 0; i < 9; i++){ wt0[i] = dww[i*256 + c]; wt1[i] = dww[i*256 + c2]; }
    float bc0 = dwb[c], bc1 = dwb[c2];

    const float* img = g_t1 + (size_t)b * HH * WW * 256;
    bool v0 = (h > 0), v2 = (h < HH-1);
    const float* r0 = img + (size_t)(h-1) * WW * 256;
    const float* r1 = img + (size_t)h     * WW * 256;
    const float* r2 = img + (size_t)(h+1) * WW * 256;

    float win0[9], win1[9];
    {
        int wm = w0 - 1;
        bool vm = (wm >= 0);
        win0[0] = (v0 && vm) ? r0[(size_t)wm*256 + c ] : 0.f;
        win0[3] =  vm        ? r1[(size_t)wm*256 + c ] : 0.f;
        win0[6] = (v2 && vm) ? r2[(size_t)wm*256 + c ] : 0.f;
        win1[0] = (v0 && vm) ? r0[(size_t)wm*256 + c2] : 0.f;
        win1[3] =  vm        ? r1[(size_t)wm*256 + c2] : 0.f;
        win1[6] = (v2 && vm) ? r2[(size_t)wm*256 + c2] : 0.f;
        win0[1] = v0 ? r0[(size_t)w0*256 + c ] : 0.f;
        win0[4] =      r1[(size_t)w0*256 + c ];
        win0[7] = v2 ? r2[(size_t)w0*256 + c ] : 0.f;
        win1[1] = v0 ? r0[(size_t)w0*256 + c2] : 0.f;
        win1[4] =      r1[(size_t)w0*256 + c2];
        win1[7] = v2 ? r2[(size_t)w0*256 + c2] : 0.f;
    }
    float* yrow = g_y + ((size_t)(b*HH + h) * WW) * 128;
    float gap = 0.f;
    for (int w = w0; w < w0 + 64; w++){
        int wp = w + 1;
        bool vp = (wp < WW);
        win0[2] = (v0 && vp) ? r0[(size_t)wp*256 + c ] : 0.f;
        win0[5] =  vp        ? r1[(size_t)wp*256 + c ] : 0.f;
        win0[8] = (v2 && vp) ? r2[(size_t)wp*256 + c ] : 0.f;
        win1[2] = (v0 && vp) ? r0[(size_t)wp*256 + c2] : 0.f;
        win1[5] =  vp        ? r1[(size_t)wp*256 + c2] : 0.f;
        win1[8] = (v2 && vp) ? r2[(size_t)wp*256 + c2] : 0.f;
        float a = bc0, bbv = bc1;
        #pragma unroll
        for (int i = 0; i < 9; i++){ a = fmaf(win0[i], wt0[i], a); bbv = fmaf(win1[i], wt1[i], bbv); }
        float yv = a * bbv;
        yrow[(size_t)w * 128 + c] = yv;
        gap += yv;
        #pragma unroll
        for (int r = 0; r < 3; r++){
            win0[r*3+0] = win0[r*3+1]; win0[r*3+1] = win0[r*3+2];
            win1[r*3+0] = win1[r*3+1]; win1[r*3+1] = win1[r*3+2];
        }
    }
    g_part[(size_t)blk * 128 + c] = gap;
}

// ---------------------------------------------------------------------------
// K3: GAP reduce + SCA (unchanged)
// ---------------------------------------------------------------------------
__global__ void k3_sca(const float* __restrict__ scaw, const float* __restrict__ scab)
{
    __shared__ float smn[128];
    int b = blockIdx.x, c = threadIdx.x;
    const float* p = g_part + (size_t)b * 1024 * 128 + c;
    float s = 0.f;
    #pragma unroll 8
    for (int i = 0; i < 1024; i++) s += p[(size_t)i * 128];
    smn[c] = s * (1.f / 65536.f);
    __syncthreads();
    float a = scab[c];
    #pragma unroll 8
    for (int k = 0; k < 128; k++) a = fmaf(smn[k], scaw[k*128 + c], a);
    g_attn[b*128 + c] = a;
}

// ---------------------------------------------------------------------------
// K4a: (y*attn) -> pw2 (128 -> 64) -> x2 = x + .*beta, tiled GEMM.
// 128 px/block, K chunked by 32. thread tile: 4 px x 8 outs.
// ---------------------------------------------------------------------------
__global__ void __launch_bounds__(256) k4a_att_pw2(
    const float* __restrict__ x, const float* __restrict__ W2,
    const float* __restrict__ b2, const float* __restrict__ beta)
{
    extern __shared__ float sm[];
    float* sW    = sm;              // 128*64 = 8192
    float* aT    = sm + 8192;       // 32*AST = 4224
    float* sA    = aT + 32*AST;     // 128
    float* sB2   = sA + 128;        // 64
    float* sBeta = sB2 + 64;        // 64
    int tid = threadIdx.x;
    int b = blockIdx.x >> 9;        // 512 blocks per image
    #pragma unroll 4
    for (int i = tid; i < 8192; i += 256) sW[i] = W2[i];
    if (tid < 128) sA[tid] = g_attn[b*128 + tid];
    else if (tid < 192) sB2[tid-128] = b2[tid-128];
    else sBeta[tid-192] = beta[tid-192];
    __syncthreads();

    size_t p0 = (size_t)blockIdx.x * PXT;
    int ip = tid & 31, jo = tid >> 5;
    int ob = jo * 8;
    u64 acc[16];
    {
        const u64* bb = (const u64*)(sB2 + ob);
        #pragma unroll
        for (int p = 0; p < 4; p++){
            acc[4*p+0]=bb[0]; acc[4*p+1]=bb[1]; acc[4*p+2]=bb[2]; acc[4*p+3]=bb[3];
        }
    }
    int lpx = tid >> 1, lco = (tid & 1) * 16;
    const float4* yp = (const float4*)(g_y + (p0 + lpx) * 128 + lco);
    const float* aBase = aT + ip * 4;
    #pragma unroll 1
    for (int kc = 0; kc < 128; kc += 32){
        // stage chunk: y * attn, transposed
        #pragma unroll
        for (int q = 0; q < 4; q++){
            float4 yv = yp[(kc >> 2) + q];
            int ch = lco + 4*q;
            aT[(ch+0)*AST + lpx] = yv.x * sA[kc+ch+0];
            aT[(ch+1)*AST + lpx] = yv.y * sA[kc+ch+1];
            aT[(ch+2)*AST + lpx] = yv.z * sA[kc+ch+2];
            aT[(ch+3)*AST + lpx] = yv.w * sA[kc+ch+3];
        }
        __syncthreads();
        const float* wBase = sW + kc*64 + ob;
        #pragma unroll 8
        for (int k = 0; k < 32; k++){
            GEMM_STEP(aBase + k*AST, wBase + k*64);
        }
        __syncthreads();
    }
    // epilogue: x + acc*beta -> g_x2
    #pragma unroll
    for (int p = 0; p < 4; p++){
        size_t px = p0 + ip*4 + p;
        const float4* xq = (const float4*)(x + px*64 + ob);
        float4 x0 = xq[0], x1 = xq[1];
        float2 r0 = unpack2(acc[4*p+0]), r1 = unpack2(acc[4*p+1]);
        float2 r2 = unpack2(acc[4*p+2]), r3 = unpack2(acc[4*p+3]);
        float4 o0, o1;
        o0.x = fmaf(r0.x, sBeta[ob+0], x0.x); o0.y = fmaf(r0.y, sBeta[ob+1], x0.y);
        o0.z = fmaf(r1.x, sBeta[ob+2], x0.z); o0.w = fmaf(r1.y, sBeta[ob+3], x0.w);
        o1.x = fmaf(r2.x, sBeta[ob+4], x1.x); o1.y = fmaf(r2.y, sBeta[ob+5], x1.y);
        o1.z = fmaf(r3.x, sBeta[ob+6], x1.z); o1.w = fmaf(r3.y, sBeta[ob+7], x1.w);
        float4* op = (float4*)(g_x2 + px*64 + ob);
        op[0] = o0; op[1] = o1;
    }
}

// ---------------------------------------------------------------------------
// K4b1: LN2 -> pw3 (64 -> 256, pair-interleaved) -> SimpleGate -> g (into g_y)
// Same tiling as k1; epilogue multiplies pairs within each f32x2 accumulator.
// ---------------------------------------------------------------------------
__global__ void __launch_bounds__(256) k4b1_ln_pw3(
    const float* __restrict__ W3, const float* __restrict__ b3,
    const float* __restrict__ g2, const float* __restrict__ bb2)
{
    extern __shared__ float sm[];
    float* sW  = sm;                 // 16384 (interleaved pairs)
    float* aT  = sm + 16384;         // 64*AST = 8448
    float* sB  = aT + 64*AST;        // 256 (interleaved)
    float* sG  = sB + 256;           // 64
    float* sBe = sG + 64;            // 64
    int tid = threadIdx.x;
    for (int i = tid; i < 16384; i += 256){
        int k = i >> 8, t = i & 255, j = t >> 1, h = t & 1;
        sW[i] = W3[k*256 + h*128 + j];
    }
    sB[tid] = b3[((tid & 1) * 128) + (tid >> 1)];
    if (tid < 64) { sG[tid] = g2[tid]; sBe[tid] = bb2[tid]; }
    __syncthreads();

    size_t p0 = (size_t)blockIdx.x * PXT;
    {
        int px = tid >> 1, half = tid & 1;
        const float4* xp = (const float4*)(g_x2 + (p0 + px) * 64 + half * 32);
        float4 v[8];
        #pragma unroll
        for (int q = 0; q < 8; q++) v[q] = xp[q];
        float s = 0.f, ss = 0.f;
        #pragma unroll
        for (int q = 0; q < 8; q++){
            float4 t = v[q];
            s += t.x + t.y + t.z + t.w;
            ss = fmaf(t.x,t.x, fmaf(t.y,t.y, fmaf(t.z,t.z, fmaf(t.w,t.w, ss))));
        }
        s  += __shfl_xor_sync(0xffffffffu, s, 1);
        ss += __shfl_xor_sync(0xffffffffu, ss, 1);
        float mean = s * (1.f/64.f);
        float var  = fmaf(-mean, mean, ss * (1.f/64.f));
        float rstd = rsqrtf(var + EPSV);
        #pragma unroll
        for (int q = 0; q < 8; q++){
            float4 t = v[q];
            int ch = half*32 + 4*q;
            aT[(ch+0)*AST + px] = fmaf((t.x-mean)*rstd, sG[ch+0], sBe[ch+0]);
            aT[(ch+1)*AST + px] = fmaf((t.y-mean)*rstd, sG[ch+1], sBe[ch+1]);
            aT[(ch+2)*AST + px] = fmaf((t.z-mean)*rstd, sG[ch+2], sBe[ch+2]);
            aT[(ch+3)*AST + px] = fmaf((t.w-mean)*rstd, sG[ch+3], sBe[ch+3]);
        }
    }
    __syncthreads();

    int ip = tid & 31, jo = tid >> 5;
    const float* aBase = aT + ip * 4;
    #pragma unroll 1
    for (int oc = 0; oc < 256; oc += 64){
        int ob = oc + jo * 8;
        u64 acc[16];
        const u64* bb = (const u64*)(sB + ob);
        #pragma unroll
        for (int p = 0; p < 4; p++){
            acc[4*p+0]=bb[0]; acc[4*p+1]=bb[1]; acc[4*p+2]=bb[2]; acc[4*p+3]=bb[3];
        }
        const float* wBase = sW + ob;
        #pragma unroll 8
        for (int k = 0; k < 64; k++){
            GEMM_STEP(aBase + k*AST, wBase + k*256);
        }
        // gate: product of pair within each u64 -> 4 floats per px
        int gb = (oc >> 1) + jo * 4;
        #pragma unroll
        for (int p = 0; p < 4; p++){
            float2 r0 = unpack2(acc[4*p+0]), r1 = unpack2(acc[4*p+1]);
            float2 r2 = unpack2(acc[4*p+2]), r3 = unpack2(acc[4*p+3]);
            float4 g4 = make_float4(r0.x*r0.y, r1.x*r1.y, r2.x*r2.y, r3.x*r3.y);
            *(float4*)(g_y + (p0 + ip*4 + p) * 128 + gb) = g4;
        }
    }
}

// ---------------------------------------------------------------------------
// K4b2: pw4 (128 -> 64) -> out = x2 + .*gamma, tiled GEMM (k4a without attn)
// ---------------------------------------------------------------------------
__global__ void __launch_bounds__(256) k4b2_pw4(
    const float* __restrict__ W4, const float* __restrict__ b4,
    const float* __restrict__ gamma, float* __restrict__ out)
{
    extern __shared__ float sm[];
    float* sW  = sm;               // 8192
    float* aT  = sm + 8192;        // 32*AST = 4224
    float* sB4 = aT + 32*AST;      // 64
    float* sGa = sB4 + 64;         // 64
    int tid = threadIdx.x;
    #pragma unroll 4
    for (int i = tid; i < 8192; i += 256) sW[i] = W4[i];
    if (tid < 64) sB4[tid] = b4[tid];
    else if (tid < 128) sGa[tid-64] = gamma[tid-64];
    __syncthreads();

    size_t p0 = (size_t)blockIdx.x * PXT;
    int ip = tid & 31, jo = tid >> 5;
    int ob = jo * 8;
    u64 acc[16];
    {
        const u64* bb = (const u64*)(sB4 + ob);
        #pragma unroll
        for (int p = 0; p < 4; p++){
            acc[4*p+0]=bb[0]; acc[4*p+1]=bb[1]; acc[4*p+2]=bb[2]; acc[4*p+3]=bb[3];
        }
    }
    int lpx = tid >> 1, lco = (tid & 1) * 16;
    const float4* yp = (const float4*)(g_y + (p0 + lpx) * 128 + lco);
    const float* aBase = aT + ip * 4;
    #pragma unroll 1
    for (int kc = 0; kc < 128; kc += 32){
        #pragma unroll
        for (int q = 0; q < 4; q++){
            float4 yv = yp[(kc >> 2) + q];
            int ch = lco + 4*q;
            aT[(ch+0)*AST + lpx] = yv.x;
            aT[(ch+1)*AST + lpx] = yv.y;
            aT[(ch+2)*AST + lpx] = yv.z;
            aT[(ch+3)*AST + lpx] = yv.w;
        }
        __syncthreads();
        const float* wBase = sW + kc*64 + ob;
        #pragma unroll 8
        for (int k = 0; k < 32; k++){
            GEMM_STEP(aBase + k*AST, wBase + k*64);
        }
        __syncthreads();
    }
    #pragma unroll
    for (int p = 0; p < 4; p++){
        size_t px = p0 + ip*4 + p;
        const float4* xq = (const float4*)(g_x2 + px*64 + ob);
        float4 x0 = xq[0], x1 = xq[1];
        float2 r0 = unpack2(acc[4*p+0]), r1 = unpack2(acc[4*p+1]);
        float2 r2 = unpack2(acc[4*p+2]), r3 = unpack2(acc[4*p+3]);
        float4 o0, o1;
        o0.x = fmaf(r0.x, sGa[ob+0], x0.x); o0.y = fmaf(r0.y, sGa[ob+1], x0.y);
        o0.z = fmaf(r1.x, sGa[ob+2], x0.z); o0.w = fmaf(r1.y, sGa[ob+3], x0.w);
        o1.x = fmaf(r2.x, sGa[ob+4], x1.x); o1.y = fmaf(r2.y, sGa[ob+5], x1.y);
        o1.z = fmaf(r3.x, sGa[ob+6], x1.z); o1.w = fmaf(r3.y, sGa[ob+7], x1.w);
        float4* op = (float4*)(out + px*64 + ob);
        op[0] = o0; op[1] = o1;
    }
}

// ---------------------------------------------------------------------------
extern "C" void kernel_launch(void* const* d_in, const int* in_sizes, int n_in,
                              void* d_out, int out_size)
{
    const float* x    = (const float*)d_in[0];
    const float* ln1g = (const float*)d_in[1];
    const float* ln1b = (const float*)d_in[2];
    const float* pw1w = (const float*)d_in[3];
    const float* pw1b = (const float*)d_in[4];
    const float* dww  = (const float*)d_in[5];
    const float* dwb  = (const float*)d_in[6];
    const float* scaw = (const float*)d_in[7];
    const float* scab = (const float*)d_in[8];
    const float* pw2w = (const float*)d_in[9];
    const float* pw2b = (const float*)d_in[10];
    const float* beta = (const float*)d_in[11];
    const float* ln2g = (const float*)d_in[12];
    const float* ln2b = (const float*)d_in[13];
    const float* pw3w = (const float*)d_in[14];
    const float* pw3b = (const float*)d_in[15];
    const float* pw4w = (const float*)d_in[16];
    const float* pw4b = (const float*)d_in[17];
    const float* gam  = (const float*)d_in[18];
    float* out = (float*)d_out;

    int smem_k1   = (16384 + 64*AST + 256 + 64 + 64) * 4;            // 100864
    int smem_k4a  = (8192 + 32*AST + 128 + 64 + 64) * 4;             // 50688
    int smem_k4b1 = smem_k1;
    int smem_k4b2 = (8192 + 32*AST + 64 + 64) * 4;                   // 50176
    cudaFuncSetAttribute(k1_ln_pw1,  cudaFuncAttributeMaxDynamicSharedMemorySize, smem_k1);
    cudaFuncSetAttribute(k4a_att_pw2, cudaFuncAttributeMaxDynamicSharedMemorySize, smem_k4a);
    cudaFuncSetAttribute(k4b1_ln_pw3, cudaFuncAttributeMaxDynamicSharedMemorySize, smem_k4b1);
    cudaFuncSetAttribute(k4b2_pw4,   cudaFuncAttributeMaxDynamicSharedMemorySize, smem_k4b2);

    k1_ln_pw1  <<<NPIX/PXT, 256, smem_k1>>>(x, ln1g, ln1b, pw1w, pw1b);
    k2_dw_gate <<<BB*1024, 128>>>(dww, dwb);
    k3_sca     <<<BB, 128>>>(scaw, scab);
    k4a_att_pw2<<<NPIX/PXT, 256, smem_k4a>>>(x, pw2w, pw2b, beta);
    k4b1_ln_pw3<<<NPIX/PXT, 256, smem_k4b1>>>(pw3w, pw3b, ln2g, ln2b);
    k4b2_pw4   <<<NPIX/PXT, 256, smem_k4b2>>>(pw4w, pw4b, gam, out);
}

// round 7
// speedup vs baseline: 1.3404x; 1.0032x over previous
#include <cuda_runtime.h>

#define EPSV 1e-6f

typedef unsigned long long u64;

__device__ __forceinline__ u64 pack2(float x, float y){
    u64 r; asm("mov.b64 %0, {%1, %2};" : "=l"(r) : "f"(x), "f"(y)); return r;
}
__device__ __forceinline__ u64 ffma2(u64 a, u64 b, u64 c){
    u64 d; asm("fma.rn.f32x2 %0, %1, %2, %3;" : "=l"(d) : "l"(a), "l"(b), "l"(c)); return d;
}
__device__ __forceinline__ float2 unpack2(u64 a){
    float2 f; asm("mov.b64 {%0, %1}, %2;" : "=f"(f.x), "=f"(f.y) : "l"(a)); return f;
}

#define BB 8
#define HH 256
#define WW 256
#define CC 64
#define HID 128
#define OC1 256
#define NPIX (BB*HH*WW)
#define PXT 128                 // pixels per GEMM block
#define AST 132                 // act tile row stride (floats): 128 + 4, 16B-aligned

// Scratch (static __device__ globals per harness rules)
__device__ float g_t1[(size_t)NPIX * OC1];   // pw1 output
__device__ float g_y [(size_t)NPIX * HID];   // gated dw output; later reused for k4b1 gate output
__device__ float g_x2[(size_t)NPIX * CC];    // stage-1 residual output
__device__ float g_part[BB * 1024 * HID];    // GAP partials per block
__device__ float g_attn[BB * HID];           // channel attention

// One register-tile GEMM step: 4 px (a4) x 8 outs (w0,w1 as 4 f32-pairs), 16 FFMA2.
#define GEMM_STEP(aPtr, wPtr) do { \
    float4 a4 = *(const float4*)(aPtr); \
    const ulonglong2* wr_ = (const ulonglong2*)(wPtr); \
    ulonglong2 w0 = wr_[0], w1 = wr_[1]; \
    u64 a0 = pack2(a4.x, a4.x), a1 = pack2(a4.y, a4.y); \
    u64 a2 = pack2(a4.z, a4.z), a3 = pack2(a4.w, a4.w); \
    acc[ 0]=ffma2(a0,w0.x,acc[ 0]); acc[ 1]=ffma2(a0,w0.y,acc[ 1]); acc[ 2]=ffma2(a0,w1.x,acc[ 2]); acc[ 3]=ffma2(a0,w1.y,acc[ 3]); \
    acc[ 4]=ffma2(a1,w0.x,acc[ 4]); acc[ 5]=ffma2(a1,w0.y,acc[ 5]); acc[ 6]=ffma2(a1,w1.x,acc[ 6]); acc[ 7]=ffma2(a1,w1.y,acc[ 7]); \
    acc[ 8]=ffma2(a2,w0.x,acc[ 8]); acc[ 9]=ffma2(a2,w0.y,acc[ 9]); acc[10]=ffma2(a2,w1.x,acc[10]); acc[11]=ffma2(a2,w1.y,acc[11]); \
    acc[12]=ffma2(a3,w0.x,acc[12]); acc[13]=ffma2(a3,w0.y,acc[13]); acc[14]=ffma2(a3,w1.x,acc[14]); acc[15]=ffma2(a3,w1.y,acc[15]); \
} while(0)

// ---------------------------------------------------------------------------
// K1: LayerNorm1 + pw1 (64 -> 256), tiled GEMM. 128 px/block, 256 threads.
// thread tile: 4 px x 8 outs; outer loop over 4 output chunks of 64.
// ---------------------------------------------------------------------------
__global__ void __launch_bounds__(256) k1_ln_pw1(
    const float* __restrict__ x, const float* __restrict__ g1,
    const float* __restrict__ b1, const float* __restrict__ W,
    const float* __restrict__ bias)
{
    extern __shared__ float sm[];
    float* sW  = sm;                 // 64*256 = 16384
    float* aT  = sm + 16384;         // 64*AST = 8448 (transposed LN tile)
    float* sB  = aT + 64*AST;        // 256
    float* sG  = sB + 256;           // 64
    float* sBe = sG + 64;            // 64
    int tid = threadIdx.x;
    #pragma unroll 4
    for (int i = tid; i < 16384; i += 256) sW[i] = W[i];
    sB[tid] = bias[tid];
    if (tid < 64) { sG[tid] = g1[tid]; sBe[tid] = b1[tid]; }
    __syncthreads();

    size_t p0 = (size_t)blockIdx.x * PXT;
    // LN: 2 threads per pixel, 32 channels each
    {
        int px = tid >> 1, half = tid & 1;
        const float4* xp = (const float4*)(x + (p0 + px) * 64 + half * 32);
        float4 v[8];
        #pragma unroll
        for (int q = 0; q < 8; q++) v[q] = xp[q];
        float s = 0.f, ss = 0.f;
        #pragma unroll
        for (int q = 0; q < 8; q++){
            float4 t = v[q];
            s += t.x + t.y + t.z + t.w;
            ss = fmaf(t.x,t.x, fmaf(t.y,t.y, fmaf(t.z,t.z, fmaf(t.w,t.w, ss))));
        }
        s  += __shfl_xor_sync(0xffffffffu, s, 1);
        ss += __shfl_xor_sync(0xffffffffu, ss, 1);
        float mean = s * (1.f/64.f);
        float var  = fmaf(-mean, mean, ss * (1.f/64.f));
        float rstd = rsqrtf(var + EPSV);
        #pragma unroll
        for (int q = 0; q < 8; q++){
            float4 t = v[q];
            int ch = half*32 + 4*q;
            aT[(ch+0)*AST + px] = fmaf((t.x-mean)*rstd, sG[ch+0], sBe[ch+0]);
            aT[(ch+1)*AST + px] = fmaf((t.y-mean)*rstd, sG[ch+1], sBe[ch+1]);
            aT[(ch+2)*AST + px] = fmaf((t.z-mean)*rstd, sG[ch+2], sBe[ch+2]);
            aT[(ch+3)*AST + px] = fmaf((t.w-mean)*rstd, sG[ch+3], sBe[ch+3]);
        }
    }
    __syncthreads();

    int ip = tid & 31, jo = tid >> 5;       // warp: same jo, ip = lane
    const float* aBase = aT + ip * 4;
    float* outBase = g_t1 + (p0 + ip * 4) * 256;
    #pragma unroll 1
    for (int oc = 0; oc < 256; oc += 64){
        int ob = oc + jo * 8;
        u64 acc[16];
        const u64* bb = (const u64*)(sB + ob);
        #pragma unroll
        for (int p = 0; p < 4; p++){
            acc[4*p+0]=bb[0]; acc[4*p+1]=bb[1]; acc[4*p+2]=bb[2]; acc[4*p+3]=bb[3];
        }
        const float* wBase = sW + ob;
        #pragma unroll 8
        for (int k = 0; k < 64; k++){
            GEMM_STEP(aBase + k*AST, wBase + k*256);
        }
        #pragma unroll
        for (int p = 0; p < 4; p++){
            float2 r0 = unpack2(acc[4*p+0]), r1 = unpack2(acc[4*p+1]);
            float2 r2 = unpack2(acc[4*p+2]), r3 = unpack2(acc[4*p+3]);
            float4* op = (float4*)(outBase + (size_t)p*256 + ob);
            op[0] = make_float4(r0.x, r0.y, r1.x, r1.y);
            op[1] = make_float4(r2.x, r2.y, r3.x, r3.y);
        }
    }
}

// ---------------------------------------------------------------------------
// K2: depthwise 3x3 (SAME) + SimpleGate + GAP partials (unchanged)
// ---------------------------------------------------------------------------
__global__ void k2_dw_gate(const float* __restrict__ dww, const float* __restrict__ dwb)
{
    int blk = blockIdx.x;           // b*1024 + h*4 + wt
    int b   = blk >> 10;
    int rem = blk & 1023;
    int h   = rem >> 2;
    int w0  = (rem & 3) << 6;
    int c   = threadIdx.x;          // 0..127
    int c2  = c + 128;
    float wt0[9], wt1[9];
    #pragma unroll
    for (int i = 0; i < 9; i++){ wt0[i] = dww[i*256 + c]; wt1[i] = dww[i*256 + c2]; }
    float bc0 = dwb[c], bc1 = dwb[c2];

    const float* img = g_t1 + (size_t)b * HH * WW * 256;
    bool v0 = (h > 0), v2 = (h < HH-1);
    const float* r0 = img + (size_t)(h-1) * WW * 256;
    const float* r1 = img + (size_t)h     * WW * 256;
    const float* r2 = img + (size_t)(h+1) * WW * 256;

    float win0[9], win1[9];
    {
        int wm = w0 - 1;
        bool vm = (wm >= 0);
        win0[0] = (v0 && vm) ? r0[(size_t)wm*256 + c ] : 0.f;
        win0[3] =  vm        ? r1[(size_t)wm*256 + c ] : 0.f;
        win0[6] = (v2 && vm) ? r2[(size_t)wm*256 + c ] : 0.f;
        win1[0] = (v0 && vm) ? r0[(size_t)wm*256 + c2] : 0.f;
        win1[3] =  vm        ? r1[(size_t)wm*256 + c2] : 0.f;
        win1[6] = (v2 && vm) ? r2[(size_t)wm*256 + c2] : 0.f;
        win0[1] = v0 ? r0[(size_t)w0*256 + c ] : 0.f;
        win0[4] =      r1[(size_t)w0*256 + c ];
        win0[7] = v2 ? r2[(size_t)w0*256 + c ] : 0.f;
        win1[1] = v0 ? r0[(size_t)w0*256 + c2] : 0.f;
        win1[4] =      r1[(size_t)w0*256 + c2];
        win1[7] = v2 ? r2[(size_t)w0*256 + c2] : 0.f;
    }
    float* yrow = g_y + ((size_t)(b*HH + h) * WW) * 128;
    float gap = 0.f;
    for (int w = w0; w < w0 + 64; w++){
        int wp = w + 1;
        bool vp = (wp < WW);
        win0[2] = (v0 && vp) ? r0[(size_t)wp*256 + c ] : 0.f;
        win0[5] =  vp        ? r1[(size_t)wp*256 + c ] : 0.f;
        win0[8] = (v2 && vp) ? r2[(size_t)wp*256 + c ] : 0.f;
        win1[2] = (v0 && vp) ? r0[(size_t)wp*256 + c2] : 0.f;
        win1[5] =  vp        ? r1[(size_t)wp*256 + c2] : 0.f;
        win1[8] = (v2 && vp) ? r2[(size_t)wp*256 + c2] : 0.f;
        float a = bc0, bbv = bc1;
        #pragma unroll
        for (int i = 0; i < 9; i++){ a = fmaf(win0[i], wt0[i], a); bbv = fmaf(win1[i], wt1[i], bbv); }
        float yv = a * bbv;
        yrow[(size_t)w * 128 + c] = yv;
        gap += yv;
        #pragma unroll
        for (int r = 0; r < 3; r++){
            win0[r*3+0] = win0[r*3+1]; win0[r*3+1] = win0[r*3+2];
            win1[r*3+0] = win1[r*3+1]; win1[r*3+1] = win1[r*3+2];
        }
    }
    g_part[(size_t)blk * 128 + c] = gap;
}

// ---------------------------------------------------------------------------
// K3: GAP reduce + SCA (unchanged)
// ---------------------------------------------------------------------------
__global__ void k3_sca(const float* __restrict__ scaw, const float* __restrict__ scab)
{
    __shared__ float smn[128];
    int b = blockIdx.x, c = threadIdx.x;
    const float* p = g_part + (size_t)b * 1024 * 128 + c;
    float s = 0.f;
    #pragma unroll 8
    for (int i = 0; i < 1024; i++) s += p[(size_t)i * 128];
    smn[c] = s * (1.f / 65536.f);
    __syncthreads();
    float a = scab[c];
    #pragma unroll 8
    for (int k = 0; k < 128; k++) a = fmaf(smn[k], scaw[k*128 + c], a);
    g_attn[b*128 + c] = a;
}

// ---------------------------------------------------------------------------
// K4a: (y*attn) -> pw2 (128 -> 64) -> x2 = x + .*beta, tiled GEMM.
// 128 px/block, K chunked by 32. thread tile: 4 px x 8 outs.
// ---------------------------------------------------------------------------
__global__ void __launch_bounds__(256) k4a_att_pw2(
    const float* __restrict__ x, const float* __restrict__ W2,
    const float* __restrict__ b2, const float* __restrict__ beta)
{
    extern __shared__ float sm[];
    float* sW    = sm;              // 128*64 = 8192
    float* aT    = sm + 8192;       // 32*AST = 4224
    float* sA    = aT + 32*AST;     // 128
    float* sB2   = sA + 128;        // 64
    float* sBeta = sB2 + 64;        // 64
    int tid = threadIdx.x;
    int b = blockIdx.x >> 9;        // 512 blocks per image
    #pragma unroll 4
    for (int i = tid; i < 8192; i += 256) sW[i] = W2[i];
    if (tid < 128) sA[tid] = g_attn[b*128 + tid];
    else if (tid < 192) sB2[tid-128] = b2[tid-128];
    else sBeta[tid-192] = beta[tid-192];
    __syncthreads();

    size_t p0 = (size_t)blockIdx.x * PXT;
    int ip = tid & 31, jo = tid >> 5;
    int ob = jo * 8;
    u64 acc[16];
    {
        const u64* bb = (const u64*)(sB2 + ob);
        #pragma unroll
        for (int p = 0; p < 4; p++){
            acc[4*p+0]=bb[0]; acc[4*p+1]=bb[1]; acc[4*p+2]=bb[2]; acc[4*p+3]=bb[3];
        }
    }
    int lpx = tid >> 1, lco = (tid & 1) * 16;
    const float4* yp = (const float4*)(g_y + (p0 + lpx) * 128 + lco);
    const float* aBase = aT + ip * 4;
    #pragma unroll 1
    for (int kc = 0; kc < 128; kc += 32){
        // stage chunk: y * attn, transposed
        #pragma unroll
        for (int q = 0; q < 4; q++){
            float4 yv = yp[(kc >> 2) + q];
            int ch = lco + 4*q;
            aT[(ch+0)*AST + lpx] = yv.x * sA[kc+ch+0];
            aT[(ch+1)*AST + lpx] = yv.y * sA[kc+ch+1];
            aT[(ch+2)*AST + lpx] = yv.z * sA[kc+ch+2];
            aT[(ch+3)*AST + lpx] = yv.w * sA[kc+ch+3];
        }
        __syncthreads();
        const float* wBase = sW + kc*64 + ob;
        #pragma unroll 8
        for (int k = 0; k < 32; k++){
            GEMM_STEP(aBase + k*AST, wBase + k*64);
        }
        __syncthreads();
    }
    // epilogue: x + acc*beta -> g_x2
    #pragma unroll
    for (int p = 0; p < 4; p++){
        size_t px = p0 + ip*4 + p;
        const float4* xq = (const float4*)(x + px*64 + ob);
        float4 x0 = xq[0], x1 = xq[1];
        float2 r0 = unpack2(acc[4*p+0]), r1 = unpack2(acc[4*p+1]);
        float2 r2 = unpack2(acc[4*p+2]), r3 = unpack2(acc[4*p+3]);
        float4 o0, o1;
        o0.x = fmaf(r0.x, sBeta[ob+0], x0.x); o0.y = fmaf(r0.y, sBeta[ob+1], x0.y);
        o0.z = fmaf(r1.x, sBeta[ob+2], x0.z); o0.w = fmaf(r1.y, sBeta[ob+3], x0.w);
        o1.x = fmaf(r2.x, sBeta[ob+4], x1.x); o1.y = fmaf(r2.y, sBeta[ob+5], x1.y);
        o1.z = fmaf(r3.x, sBeta[ob+6], x1.z); o1.w = fmaf(r3.y, sBeta[ob+7], x1.w);
        float4* op = (float4*)(g_x2 + px*64 + ob);
        op[0] = o0; op[1] = o1;
    }
}

// ---------------------------------------------------------------------------
// K4b1: LN2 -> pw3 (64 -> 256, pair-interleaved) -> SimpleGate -> g (into g_y)
// Same tiling as k1; epilogue multiplies pairs within each f32x2 accumulator.
// ---------------------------------------------------------------------------
__global__ void __launch_bounds__(256) k4b1_ln_pw3(
    const float* __restrict__ W3, const float* __restrict__ b3,
    const float* __restrict__ g2, const float* __restrict__ bb2)
{
    extern __shared__ float sm[];
    float* sW  = sm;                 // 16384 (interleaved pairs)
    float* aT  = sm + 16384;         // 64*AST = 8448
    float* sB  = aT + 64*AST;        // 256 (interleaved)
    float* sG  = sB + 256;           // 64
    float* sBe = sG + 64;            // 64
    int tid = threadIdx.x;
    for (int i = tid; i < 16384; i += 256){
        int k = i >> 8, t = i & 255, j = t >> 1, h = t & 1;
        sW[i] = W3[k*256 + h*128 + j];
    }
    sB[tid] = b3[((tid & 1) * 128) + (tid >> 1)];
    if (tid < 64) { sG[tid] = g2[tid]; sBe[tid] = bb2[tid]; }
    __syncthreads();

    size_t p0 = (size_t)blockIdx.x * PXT;
    {
        int px = tid >> 1, half = tid & 1;
        const float4* xp = (const float4*)(g_x2 + (p0 + px) * 64 + half * 32);
        float4 v[8];
        #pragma unroll
        for (int q = 0; q < 8; q++) v[q] = xp[q];
        float s = 0.f, ss = 0.f;
        #pragma unroll
        for (int q = 0; q < 8; q++){
            float4 t = v[q];
            s += t.x + t.y + t.z + t.w;
            ss = fmaf(t.x,t.x, fmaf(t.y,t.y, fmaf(t.z,t.z, fmaf(t.w,t.w, ss))));
        }
        s  += __shfl_xor_sync(0xffffffffu, s, 1);
        ss += __shfl_xor_sync(0xffffffffu, ss, 1);
        float mean = s * (1.f/64.f);
        float var  = fmaf(-mean, mean, ss * (1.f/64.f));
        float rstd = rsqrtf(var + EPSV);
        #pragma unroll
        for (int q = 0; q < 8; q++){
            float4 t = v[q];
            int ch = half*32 + 4*q;
            aT[(ch+0)*AST + px] = fmaf((t.x-mean)*rstd, sG[ch+0], sBe[ch+0]);
            aT[(ch+1)*AST + px] = fmaf((t.y-mean)*rstd, sG[ch+1], sBe[ch+1]);
            aT[(ch+2)*AST + px] = fmaf((t.z-mean)*rstd, sG[ch+2], sBe[ch+2]);
            aT[(ch+3)*AST + px] = fmaf((t.w-mean)*rstd, sG[ch+3], sBe[ch+3]);
        }
    }
    __syncthreads();

    int ip = tid & 31, jo = tid >> 5;
    const float* aBase = aT + ip * 4;
    #pragma unroll 1
    for (int oc = 0; oc < 256; oc += 64){
        int ob = oc + jo * 8;
        u64 acc[16];
        const u64* bb = (const u64*)(sB + ob);
        #pragma unroll
        for (int p = 0; p < 4; p++){
            acc[4*p+0]=bb[0]; acc[4*p+1]=bb[1]; acc[4*p+2]=bb[2]; acc[4*p+3]=bb[3];
        }
        const float* wBase = sW + ob;
        #pragma unroll 8
        for (int k = 0; k < 64; k++){
            GEMM_STEP(aBase + k*AST, wBase + k*256);
        }
        // gate: product of pair within each u64 -> 4 floats per px
        int gb = (oc >> 1) + jo * 4;
        #pragma unroll
        for (int p = 0; p < 4; p++){
            float2 r0 = unpack2(acc[4*p+0]), r1 = unpack2(acc[4*p+1]);
            float2 r2 = unpack2(acc[4*p+2]), r3 = unpack2(acc[4*p+3]);
            float4 g4 = make_float4(r0.x*r0.y, r1.x*r1.y, r2.x*r2.y, r3.x*r3.y);
            *(float4*)(g_y + (p0 + ip*4 + p) * 128 + gb) = g4;
        }
    }
}

// ---------------------------------------------------------------------------
// K4b2: pw4 (128 -> 64) -> out = x2 + .*gamma, tiled GEMM (k4a without attn)
// ---------------------------------------------------------------------------
__global__ void __launch_bounds__(256) k4b2_pw4(
    const float* __restrict__ W4, const float* __restrict__ b4,
    const float* __restrict__ gamma, float* __restrict__ out)
{
    extern __shared__ float sm[];
    float* sW  = sm;               // 8192
    float* aT  = sm + 8192;        // 32*AST = 4224
    float* sB4 = aT + 32*AST;      // 64
    float* sGa = sB4 + 64;         // 64
    int tid = threadIdx.x;
    #pragma unroll 4
    for (int i = tid; i < 8192; i += 256) sW[i] = W4[i];
    if (tid < 64) sB4[tid] = b4[tid];
    else if (tid < 128) sGa[tid-64] = gamma[tid-64];
    __syncthreads();

    size_t p0 = (size_t)blockIdx.x * PXT;
    int ip = tid & 31, jo = tid >> 5;
    int ob = jo * 8;
    u64 acc[16];
    {
        const u64* bb = (const u64*)(sB4 + ob);
        #pragma unroll
        for (int p = 0; p < 4; p++){
            acc[4*p+0]=bb[0]; acc[4*p+1]=bb[1]; acc[4*p+2]=bb[2]; acc[4*p+3]=bb[3];
        }
    }
    int lpx = tid >> 1, lco = (tid & 1) * 16;
    const float4* yp = (const float4*)(g_y + (p0 + lpx) * 128 + lco);
    const float* aBase = aT + ip * 4;
    #pragma unroll 1
    for (int kc = 0; kc < 128; kc += 32){
        #pragma unroll
        for (int q = 0; q < 4; q++){
            float4 yv = yp[(kc >> 2) + q];
            int ch = lco + 4*q;
            aT[(ch+0)*AST + lpx] = yv.x;
            aT[(ch+1)*AST + lpx] = yv.y;
            aT[(ch+2)*AST + lpx] = yv.z;
            aT[(ch+3)*AST + lpx] = yv.w;
        }
        __syncthreads();
        const float* wBase = sW + kc*64 + ob;
        #pragma unroll 8
        for (int k = 0; k < 32; k++){
            GEMM_STEP(aBase + k*AST, wBase + k*64);
        }
        __syncthreads();
    }
    #pragma unroll
    for (int p = 0; p < 4; p++){
        size_t px = p0 + ip*4 + p;
        const float4* xq = (const float4*)(g_x2 + px*64 + ob);
        float4 x0 = xq[0], x1 = xq[1];
        float2 r0 = unpack2(acc[4*p+0]), r1 = unpack2(acc[4*p+1]);
        float2 r2 = unpack2(acc[4*p+2]), r3 = unpack2(acc[4*p+3]);
        float4 o0, o1;
        o0.x = fmaf(r0.x, sGa[ob+0], x0.x); o0.y = fmaf(r0.y, sGa[ob+1], x0.y);
        o0.z = fmaf(r1.x, sGa[ob+2], x0.z); o0.w = fmaf(r1.y, sGa[ob+3], x0.w);
        o1.x = fmaf(r2.x, sGa[ob+4], x1.x); o1.y = fmaf(r2.y, sGa[ob+5], x1.y);
        o1.z = fmaf(r3.x, sGa[ob+6], x1.z); o1.w = fmaf(r3.y, sGa[ob+7], x1.w);
        float4* op = (float4*)(out + px*64 + ob);
        op[0] = o0; op[1] = o1;
    }
}

// ---------------------------------------------------------------------------
extern "C" void kernel_launch(void* const* d_in, const int* in_sizes, int n_in,
                              void* d_out, int out_size)
{
    const float* x    = (const float*)d_in[0];
    const float* ln1g = (const float*)d_in[1];
    const float* ln1b = (const float*)d_in[2];
    const float* pw1w = (const float*)d_in[3];
    const float* pw1b = (const float*)d_in[4];
    const float* dww  = (const float*)d_in[5];
    const float* dwb  = (const float*)d_in[6];
    const float* scaw = (const float*)d_in[7];
    const float* scab = (const float*)d_in[8];
    const float* pw2w = (const float*)d_in[9];
    const float* pw2b = (const float*)d_in[10];
    const float* beta = (const float*)d_in[11];
    const float* ln2g = (const float*)d_in[12];
    const float* ln2b = (const float*)d_in[13];
    const float* pw3w = (const float*)d_in[14];
    const float* pw3b = (const float*)d_in[15];
    const float* pw4w = (const float*)d_in[16];
    const float* pw4b = (const float*)d_in[17];
    const float* gam  = (const float*)d_in[18];
    float* out = (float*)d_out;

    int smem_k1   = (16384 + 64*AST + 256 + 64 + 64) * 4;            // 100864
    int smem_k4a  = (8192 + 32*AST + 128 + 64 + 64) * 4;             // 50688
    int smem_k4b1 = smem_k1;
    int smem_k4b2 = (8192 + 32*AST + 64 + 64) * 4;                   // 50176
    cudaFuncSetAttribute(k1_ln_pw1,  cudaFuncAttributeMaxDynamicSharedMemorySize, smem_k1);
    cudaFuncSetAttribute(k4a_att_pw2, cudaFuncAttributeMaxDynamicSharedMemorySize, smem_k4a);
    cudaFuncSetAttribute(k4b1_ln_pw3, cudaFuncAttributeMaxDynamicSharedMemorySize, smem_k4b1);
    cudaFuncSetAttribute(k4b2_pw4,   cudaFuncAttributeMaxDynamicSharedMemorySize, smem_k4b2);

    k1_ln_pw1  <<<NPIX/PXT, 256, smem_k1>>>(x, ln1g, ln1b, pw1w, pw1b);
    k2_dw_gate <<<BB*1024, 128>>>(dww, dwb);
    k3_sca     <<<BB, 128>>>(scaw, scab);
    k4a_att_pw2<<<NPIX/PXT, 256, smem_k4a>>>(x, pw2w, pw2b, beta);
    k4b1_ln_pw3<<<NPIX/PXT, 256, smem_k4b1>>>(pw3w, pw3b, ln2g, ln2b);
    k4b2_pw4   <<<NPIX/PXT, 256, smem_k4b2>>>(pw4w, pw4b, gam, out);
}